// round 1
// baseline (speedup 1.0000x reference)
#include <cuda_runtime.h>
#include <cstdint>

// chamfer_distance: B=4,S=4 pairs; N=M=4096 3D points per pair.
// out[s*B+b] = mean_n min_m d2 + mean_m min_n d2.
//
// Strategy: per (b,s) pair, load the full target set into SMEM as SoA
// (x, y, z, h=0.5*|y|^2). Each thread owns QPT query points in registers
// (negated, duplicated into f32x2 pairs). Inner loop processes TWO targets
// per iteration via LDS.64 + 3x fma.rn.f32x2 (packed fp32 FMA, 2x fp32
// throughput on sm_103a). Running mins kept per target-stream on the ALU
// pipe (FMNMX), combined at the end: d2 = max(x2 + 2*min_t, 0).

#define BDIM 4
#define SDIM 4
#define NPAIRS (BDIM * SDIM)
#define THREADS 128
#define QPT 4  // queries per thread

__device__ __forceinline__ uint64_t fma2(uint64_t a, uint64_t b, uint64_t c) {
    uint64_t d;
    asm("fma.rn.f32x2 %0, %1, %2, %3;" : "=l"(d) : "l"(a), "l"(b), "l"(c));
    return d;
}
__device__ __forceinline__ uint64_t pack2(float lo, float hi) {
    uint64_t d;
    asm("mov.b64 %0, {%1, %2};" : "=l"(d) : "f"(lo), "f"(hi));
    return d;
}
__device__ __forceinline__ void unpack2(uint64_t v, float& lo, float& hi) {
    asm("mov.b64 {%0, %1}, %2;" : "=f"(lo), "=f"(hi) : "l"(v));
}

extern __shared__ float s_mem[];

__global__ __launch_bounds__(THREADS)
void chamfer_dir_kernel(const float* __restrict__ qpts,
                        const float* __restrict__ tpts,
                        int Nq, int Mt, float inv_n,
                        float* __restrict__ out) {
    const int pair = blockIdx.y;
    const int Ms = (Mt + 1) & ~1;  // even stride so each SoA array is 8B-aligned
    float* sx = s_mem;
    float* sy = s_mem + Ms;
    float* sz = s_mem + 2 * Ms;
    float* sh = s_mem + 3 * Ms;

    // ---- Stage targets into SMEM (SoA + half-squared-norm) ----
    const float* tbase = tpts + (size_t)pair * Mt * 3;
    for (int j = threadIdx.x; j < Mt; j += THREADS) {
        float a = tbase[3 * j + 0];
        float b = tbase[3 * j + 1];
        float c = tbase[3 * j + 2];
        sx[j] = a; sy[j] = b; sz[j] = c;
        sh[j] = 0.5f * (a * a + b * b + c * c);
    }
    if (Mt & 1) {
        // pad the duplicate slot with a far-away sentinel so the packed lane
        // never wins the min
        if (threadIdx.x == 0) {
            sx[Mt] = 0.f; sy[Mt] = 0.f; sz[Mt] = 0.f; sh[Mt] = 3.0e38f;
        }
    }
    __syncthreads();

    // ---- Query register setup ----
    uint64_t nx[QPT], ny[QPT], nz[QPT];
    float x2[QPT], mlo[QPT], mhi[QPT];
    const float* qbase = qpts + (size_t)pair * Nq * 3;
    const int q0 = blockIdx.x * (THREADS * QPT) + threadIdx.x;
#pragma unroll
    for (int k = 0; k < QPT; k++) {
        int qi = q0 + k * THREADS;
        float a = 0.f, b = 0.f, c = 0.f;
        if (qi < Nq) {
            a = qbase[3 * qi + 0];
            b = qbase[3 * qi + 1];
            c = qbase[3 * qi + 2];
        }
        nx[k] = pack2(-a, -a);
        ny[k] = pack2(-b, -b);
        nz[k] = pack2(-c, -c);
        x2[k] = a * a + b * b + c * c;
        mlo[k] = 3.0e38f;
        mhi[k] = 3.0e38f;
    }

    // ---- Main loop: 2 targets / iteration via packed f32x2 FMA ----
    const uint64_t* px = (const uint64_t*)sx;
    const uint64_t* py = (const uint64_t*)sy;
    const uint64_t* pz = (const uint64_t*)sz;
    const uint64_t* ph = (const uint64_t*)sh;
    const int half = Ms >> 1;
#pragma unroll 4
    for (int j = 0; j < half; j++) {
        uint64_t bx = px[j];
        uint64_t by = py[j];
        uint64_t bz = pz[j];
        uint64_t hh = ph[j];
#pragma unroll
        for (int k = 0; k < QPT; k++) {
            uint64_t t = fma2(nx[k], bx, hh);  // h - x*tx
            t = fma2(ny[k], by, t);            //   - y*ty
            t = fma2(nz[k], bz, t);            //   - z*tz
            float lo, hi;
            unpack2(t, lo, hi);
            mlo[k] = fminf(mlo[k], lo);
            mhi[k] = fminf(mhi[k], hi);
        }
    }

    // ---- Finalize: d2 = max(x2 + 2*min_t, 0), sum over this thread's queries
    float lsum = 0.f;
#pragma unroll
    for (int k = 0; k < QPT; k++) {
        int qi = q0 + k * THREADS;
        if (qi < Nq) {
            float t = fminf(mlo[k], mhi[k]);
            float d2 = fmaxf(fmaf(2.0f, t, x2[k]), 0.0f);
            lsum += d2;
        }
    }

    // ---- Warp reduce + atomic accumulate (mean) ----
#pragma unroll
    for (int off = 16; off; off >>= 1)
        lsum += __shfl_down_sync(0xffffffffu, lsum, off);
    if ((threadIdx.x & 31) == 0) {
        int b = pair / SDIM;
        int s = pair % SDIM;
        atomicAdd(out + s * BDIM + b, lsum * inv_n);
    }
}

extern "C" void kernel_launch(void* const* d_in, const int* in_sizes, int n_in,
                              void* d_out, int out_size) {
    const float* outp = (const float*)d_in[0];  // output_points [B,S,N,3]
    const float* tgtp = (const float*)d_in[1];  // target_points [B,S,M,3]
    float* out = (float*)d_out;                  // [S,B] fp32

    const int Nq = in_sizes[0] / (NPAIRS * 3);
    const int Mt = in_sizes[1] / (NPAIRS * 3);
    const int Ns = (Nq + 1) & ~1;
    const int Msv = (Mt + 1) & ~1;
    const size_t smem1 = (size_t)4 * Msv * sizeof(float);  // dir 0 stages targets
    const size_t smem2 = (size_t)4 * Ns * sizeof(float);   // dir 1 stages outputs
    const size_t smax = smem1 > smem2 ? smem1 : smem2;

    cudaFuncSetAttribute(chamfer_dir_kernel,
                         cudaFuncAttributeMaxDynamicSharedMemorySize, (int)smax);

    // d_out is poisoned; both directions accumulate into it
    cudaMemsetAsync(out, 0, (size_t)out_size * sizeof(float));

    const int qpb = THREADS * QPT;  // queries per block
    dim3 grid1((Nq + qpb - 1) / qpb, NPAIRS);
    chamfer_dir_kernel<<<grid1, THREADS, smem1>>>(outp, tgtp, Nq, Mt,
                                                  1.0f / (float)Nq, out);
    dim3 grid2((Mt + qpb - 1) / qpb, NPAIRS);
    chamfer_dir_kernel<<<grid2, THREADS, smem2>>>(tgtp, outp, Mt, Nq,
                                                  1.0f / (float)Mt, out);
}

// round 2
// speedup vs baseline: 2.1589x; 2.1589x over previous
#include <cuda_runtime.h>
#include <cstdint>

// Chamfer distance, B=4,S=4 pairs, N=M=4096 3D points.
// One fused kernel: grid.z enumerates (direction x target-half). Each block
// stages HALF the target set (32KB SoA + half-norm) and evaluates QPT=4
// queries/thread against it with packed fma.rn.f32x2 (2 evals per 3 FFMA2).
// Per-query partial mins are combined across the two target-halves with
// atomicMin on the int image of the clamped (>=0) partial distance.
// A small reduce kernel then averages per (dir,pair) and accumulates out[S,B].

#define BDIM 4
#define SDIM 4
#define NPAIRS 16
#define THREADS 128
#define QPT 4
#define MAXQ 8192

__device__ int g_minbuf[2 * NPAIRS * MAXQ];  // 1 MB scratch

__device__ __forceinline__ uint64_t fma2(uint64_t a, uint64_t b, uint64_t c) {
    uint64_t d;
    asm("fma.rn.f32x2 %0, %1, %2, %3;" : "=l"(d) : "l"(a), "l"(b), "l"(c));
    return d;
}
__device__ __forceinline__ uint64_t pack2(float lo, float hi) {
    uint64_t d;
    asm("mov.b64 %0, {%1, %2};" : "=l"(d) : "f"(lo), "f"(hi));
    return d;
}
__device__ __forceinline__ void unpack2(uint64_t v, float& lo, float& hi) {
    asm("mov.b64 {%0, %1}, %2;" : "=f"(lo), "=f"(hi) : "l"(v));
}

__global__ void init_kernel(int n) {
    int i = blockIdx.x * blockDim.x + threadIdx.x;
    if (i < n) g_minbuf[i] = 0x7F000000;  // large positive float as int
}

extern __shared__ float s_mem[];

__global__ __launch_bounds__(THREADS)
void chamfer_main(const float* __restrict__ outp,
                  const float* __restrict__ tgtp,
                  int Nq, int Mt, int Ts) {
    const int dir  = blockIdx.z >> 1;   // 0: out->tgt, 1: tgt->out
    const int th   = blockIdx.z & 1;    // target half
    const int pair = blockIdx.y;

    const float* qpts = dir ? tgtp : outp;
    const float* tpts = dir ? outp : tgtp;
    const int nq = dir ? Mt : Nq;
    const int mt = dir ? Nq : Mt;

    const int halfM = (mt + 1) >> 1;
    const int tile0 = th * halfM;
    const int tn = min(halfM, mt - tile0);

    float* sx = s_mem;
    float* sy = s_mem + Ts;
    float* sz = s_mem + 2 * Ts;
    float* sh = s_mem + 3 * Ts;

    // ---- stage target half-tile: SoA + half squared norm ----
    const float* tbase = tpts + (size_t)pair * mt * 3 + (size_t)tile0 * 3;
    for (int j = threadIdx.x; j < tn; j += THREADS) {
        float a = tbase[3 * j + 0];
        float b = tbase[3 * j + 1];
        float c = tbase[3 * j + 2];
        sx[j] = a; sy[j] = b; sz[j] = c;
        sh[j] = 0.5f * (a * a + b * b + c * c);
    }
    for (int j = tn + threadIdx.x; j < Ts; j += THREADS) {
        sx[j] = 0.f; sy[j] = 0.f; sz[j] = 0.f; sh[j] = 3.0e37f;  // sentinel
    }
    __syncthreads();

    // ---- query register setup (negated, packed {v,v}) ----
    uint64_t nx[QPT], ny[QPT], nz[QPT];
    float x2[QPT], mlo[QPT], mhi[QPT];
    const float* qbase = qpts + (size_t)pair * nq * 3;
    const int q0 = blockIdx.x * (THREADS * QPT) + threadIdx.x;
#pragma unroll
    for (int k = 0; k < QPT; k++) {
        int qi = q0 + k * THREADS;
        float a = 0.f, b = 0.f, c = 0.f;
        if (qi < nq) {
            a = qbase[3 * qi + 0];
            b = qbase[3 * qi + 1];
            c = qbase[3 * qi + 2];
        }
        nx[k] = pack2(-a, -a);
        ny[k] = pack2(-b, -b);
        nz[k] = pack2(-c, -c);
        x2[k] = a * a + b * b + c * c;
        mlo[k] = 3.0e37f;
        mhi[k] = 3.0e37f;
    }

    // ---- main loop: 4 targets / iter via LDS.128 + packed f32x2 FMA ----
    const ulonglong2* pX = (const ulonglong2*)sx;
    const ulonglong2* pY = (const ulonglong2*)sy;
    const ulonglong2* pZ = (const ulonglong2*)sz;
    const ulonglong2* pH = (const ulonglong2*)sh;
    const int iters = Ts >> 2;
#pragma unroll 2
    for (int j = 0; j < iters; j++) {
        ulonglong2 BX = pX[j];
        ulonglong2 BY = pY[j];
        ulonglong2 BZ = pZ[j];
        ulonglong2 HH = pH[j];
#pragma unroll
        for (int k = 0; k < QPT; k++) {
            uint64_t t0 = fma2(nx[k], BX.x, HH.x);
            t0 = fma2(ny[k], BY.x, t0);
            t0 = fma2(nz[k], BZ.x, t0);
            uint64_t t1 = fma2(nx[k], BX.y, HH.y);
            t1 = fma2(ny[k], BY.y, t1);
            t1 = fma2(nz[k], BZ.y, t1);
            float a0, a1, b0, b1;
            unpack2(t0, a0, a1);
            unpack2(t1, b0, b1);
            mlo[k] = fminf(mlo[k], a0);
            mhi[k] = fminf(mhi[k], a1);
            mlo[k] = fminf(mlo[k], b0);
            mhi[k] = fminf(mhi[k], b1);
        }
    }

    // ---- combine partial mins across target-halves via atomicMin ----
    const int sbase = (dir ? NPAIRS * Nq : 0) + pair * nq;
#pragma unroll
    for (int k = 0; k < QPT; k++) {
        int qi = q0 + k * THREADS;
        if (qi < nq) {
            float t = fminf(mlo[k], mhi[k]);
            float v = fmaxf(fmaf(2.0f, t, x2[k]), 0.0f);  // v >= 0
            atomicMin(&g_minbuf[sbase + qi], __float_as_int(v));
        }
    }
}

__global__ void reduce_kernel(int Nq, int Mt, float* __restrict__ out) {
    const int dir = blockIdx.x >> 4;
    const int pair = blockIdx.x & 15;
    const int nq = dir ? Mt : Nq;
    const int base = (dir ? NPAIRS * Nq : 0) + pair * nq;

    float s = 0.f;
    for (int i = threadIdx.x; i < nq; i += blockDim.x)
        s += __int_as_float(g_minbuf[base + i]);

#pragma unroll
    for (int off = 16; off; off >>= 1)
        s += __shfl_down_sync(0xffffffffu, s, off);

    __shared__ float red[8];
    const int wid = threadIdx.x >> 5;
    if ((threadIdx.x & 31) == 0) red[wid] = s;
    __syncthreads();
    if (threadIdx.x == 0) {
        float tot = 0.f;
        for (int w = 0; w < (int)(blockDim.x >> 5); w++) tot += red[w];
        int b = pair / SDIM;
        int sidx = pair % SDIM;
        atomicAdd(out + sidx * BDIM + b, tot / (float)nq);
    }
}

extern "C" void kernel_launch(void* const* d_in, const int* in_sizes, int n_in,
                              void* d_out, int out_size) {
    const float* outp = (const float*)d_in[0];  // [B,S,N,3]
    const float* tgtp = (const float*)d_in[1];  // [B,S,M,3]
    float* out = (float*)d_out;                  // [S,B]

    const int Nq = in_sizes[0] / (NPAIRS * 3);
    const int Mt = in_sizes[1] / (NPAIRS * 3);
    const int maxP = Nq > Mt ? Nq : Mt;
    const int halfM = (maxP + 1) >> 1;
    const int Ts = (halfM + 3) & ~3;                 // multiple of 4 for LDS.128
    const size_t smem = (size_t)4 * Ts * sizeof(float);

    cudaFuncSetAttribute(chamfer_main,
                         cudaFuncAttributeMaxDynamicSharedMemorySize, (int)smem);

    // 1) init per-query min scratch
    const int nslots = NPAIRS * (Nq + Mt);
    init_kernel<<<(nslots + 255) / 256, 256>>>(nslots);

    // 2) fused both-direction distance kernel
    const int qpb = THREADS * QPT;
    dim3 grid((maxP + qpb - 1) / qpb, NPAIRS, 4);   // 4 = 2 dirs x 2 target halves
    chamfer_main<<<grid, THREADS, smem>>>(outp, tgtp, Nq, Mt, Ts);

    // 3) zero output, then mean-reduce both directions into it
    cudaMemsetAsync(out, 0, (size_t)out_size * sizeof(float));
    reduce_kernel<<<2 * NPAIRS, 256>>>(Nq, Mt, out);
}